// round 13
// baseline (speedup 1.0000x reference)
#include <cuda_runtime.h>
#include <cuda_bf16.h>
#include <cstdint>

// out[b] = ||xdot[b]||^2 + (xdot[b]^T W x[b])^2
//
// bf16 hi/lo split HMMA GEMM (U ~= Ah*Bh + Ah*Bl + Al*Bh, fp32 accum), then
// t[b] = sum_n U[b,n] x[b,n]. Two launches:
//  L1 (stm_prep): xdot -> (Ah, Al) + ||xdot||^2 ; W -> transposed (Bh, Bl);
//                 zero per-b-tile completion counters
//  L2 (stm_mma):  HMMA GEMM, CTA tile 128x64, k-split 4 (K=128/CTA, 4 chunks),
//                 256 CTAs -> 2 CTAs/SM for latency hiding. Fused bilinear
//                 epilogue -> deterministic partials; last of the 32 CTAs per
//                 b-tile sums the fixed slots in fixed order and writes out.

#define NB 1024
#define ND 512
#define BM 128
#define BN 64
#define BKC 32            // k per chunk
#define KS 128            // k per CTA (4 chunks)
#define NCH 4
#define LDU 66            // fp32 elems per Us row

// ---------------- scratch ----------------
__device__ __nv_bfloat16 g_Ah[NB * ND];
__device__ __nv_bfloat16 g_Al[NB * ND];
__device__ __nv_bfloat16 g_Bh[ND * ND];   // [n][j] = hi(W[j][n])
__device__ __nv_bfloat16 g_Bl[ND * ND];
__device__ float g_norm[NB];
__device__ float g_partial[32 * NB];
__device__ unsigned g_ctr[8];

// smem stage layout (bytes): Ah 10240 | Al 10240 | Bh 5120 | Bl 5120 = 30720
#define ST_AH 0
#define ST_AL 10240
#define ST_BH 20480
#define ST_BL 25600
#define STAGE 30720
#define SMEM_MMA (2 * STAGE)   // 61440; Us (128*66*4=33792) reuses buf0 region

// ---------------- PTX helpers ----------------
__device__ __forceinline__ uint32_t smem_u32(const void* p) {
    uint32_t a;
    asm("{ .reg .u64 t; cvta.to.shared.u64 t, %1; cvt.u32.u64 %0, t; }"
        : "=r"(a) : "l"(p));
    return a;
}
__device__ __forceinline__ void cpa16(uint32_t dst, const void* src) {
    asm volatile("cp.async.cg.shared.global [%0], [%1], 16;\n" :: "r"(dst), "l"(src));
}
#define CP_COMMIT() asm volatile("cp.async.commit_group;\n" ::: "memory")
#define CP_WAIT(n)  asm volatile("cp.async.wait_group %0;\n" :: "n"(n) : "memory")

__device__ __forceinline__ void ldsm_x4(uint32_t& r0, uint32_t& r1,
                                        uint32_t& r2, uint32_t& r3, uint32_t addr) {
    asm volatile("ldmatrix.sync.aligned.m8n8.x4.shared.b16 {%0,%1,%2,%3}, [%4];"
                 : "=r"(r0), "=r"(r1), "=r"(r2), "=r"(r3) : "r"(addr));
}
__device__ __forceinline__ void mma16816(float* c, const uint32_t* a, const uint32_t* b) {
    asm volatile("mma.sync.aligned.m16n8k16.row.col.f32.bf16.bf16.f32 "
                 "{%0,%1,%2,%3}, {%4,%5,%6,%7}, {%8,%9}, {%0,%1,%2,%3};"
                 : "+f"(c[0]), "+f"(c[1]), "+f"(c[2]), "+f"(c[3])
                 : "r"(a[0]), "r"(a[1]), "r"(a[2]), "r"(a[3]), "r"(b[0]), "r"(b[1]));
}

// ---------------- L1: fused convert (A + norms | B transpose) ----------------
__global__ __launch_bounds__(256)
void stm_prep(const float* __restrict__ xd, const float* __restrict__ W) {
    if (blockIdx.x < 128) {
        if (blockIdx.x == 0 && threadIdx.x < 8) g_ctr[threadIdx.x] = 0u;
        int wid = threadIdx.x >> 5, lane = threadIdx.x & 31;
        int b = blockIdx.x * 8 + wid;
        const float4* xr = (const float4*)(xd + (size_t)b * ND);
        __nv_bfloat162* ah = (__nv_bfloat162*)(g_Ah + (size_t)b * ND);
        __nv_bfloat162* al = (__nv_bfloat162*)(g_Al + (size_t)b * ND);
        float n2 = 0.0f;
#pragma unroll
        for (int p = 0; p < 4; p++) {
            int q = lane + 32 * p;
            float4 v = xr[q];
            n2 += v.x * v.x + v.y * v.y + v.z * v.z + v.w * v.w;
            __nv_bfloat16 hx = __float2bfloat16(v.x), hy = __float2bfloat16(v.y);
            __nv_bfloat16 hz = __float2bfloat16(v.z), hw = __float2bfloat16(v.w);
            ah[q * 2 + 0] = __halves2bfloat162(hx, hy);
            ah[q * 2 + 1] = __halves2bfloat162(hz, hw);
            al[q * 2 + 0] = __halves2bfloat162(__float2bfloat16(v.x - __bfloat162float(hx)),
                                               __float2bfloat16(v.y - __bfloat162float(hy)));
            al[q * 2 + 1] = __halves2bfloat162(__float2bfloat16(v.z - __bfloat162float(hz)),
                                               __float2bfloat16(v.w - __bfloat162float(hw)));
        }
#pragma unroll
        for (int o = 16; o > 0; o >>= 1) n2 += __shfl_xor_sync(0xffffffffu, n2, o);
        if (lane == 0) g_norm[b] = n2;
    } else {
        __shared__ float s[32][33];
        int bi = blockIdx.x - 128;              // 0..255
        int n0 = (bi & 15) * 32, j0 = (bi >> 4) * 32;
        int tx = threadIdx.x & 31, ty = threadIdx.x >> 5;
#pragma unroll
        for (int i = 0; i < 4; i++) {
            int r = ty + 8 * i;
            s[r][tx] = W[(size_t)(j0 + r) * ND + n0 + tx];
        }
        __syncthreads();
#pragma unroll
        for (int i = 0; i < 4; i++) {
            int r = ty + 8 * i;                 // local n
            float v = s[tx][r];                 // = W[j0+tx][n0+r]
            __nv_bfloat16 h = __float2bfloat16(v);
            size_t o = (size_t)(n0 + r) * ND + j0 + tx;
            g_Bh[o] = h;
            g_Bl[o] = __float2bfloat16(v - __bfloat162float(h));
        }
    }
}

// ---------------- L2: HMMA GEMM + fused epilogue + finalize ----------------
__device__ __forceinline__ void load_chunk(uint32_t sb, int stage, int b0, int n0,
                                           int kc, int tid) {
    uint32_t base = sb + stage * STAGE;
#pragma unroll
    for (int p = 0; p < 2; p++) {
        int idx = tid + p * 256;            // 0..511
        int row = idx >> 2, c = idx & 3;    // row 0..127, 16B chunk 0..3
        uint32_t d = base + row * 80 + c * 16;
        size_t off = (size_t)(b0 + row) * ND + kc + c * 8;
        cpa16(d + ST_AH, g_Ah + off);
        cpa16(d + ST_AL, g_Al + off);
    }
    {
        int row = tid >> 2, c = tid & 3;    // row 0..63
        uint32_t d = base + row * 80 + c * 16;
        size_t off = (size_t)(n0 + row) * ND + kc + c * 8;
        cpa16(d + ST_BH, g_Bh + off);
        cpa16(d + ST_BL, g_Bl + off);
    }
}

__global__ __launch_bounds__(256, 2)
void stm_mma(const float* __restrict__ x, float* __restrict__ out) {
    extern __shared__ __align__(128) char smem[];
    uint32_t sb = smem_u32(smem);
    const int tid = threadIdx.x, wid = tid >> 5, lane = tid & 31;
    const int wm = wid & 3, wn = wid >> 2;       // warp tile (32m x 32n)
    const int n0 = blockIdx.x * BN;
    const int b0 = blockIdx.y * BM;
    const int kz = blockIdx.z;
    const int kbase = kz * KS;

    float c[2][4][4];
#pragma unroll
    for (int i = 0; i < 2; i++)
#pragma unroll
        for (int j = 0; j < 4; j++)
#pragma unroll
            for (int r = 0; r < 4; r++) c[i][j][r] = 0.0f;

    load_chunk(sb, 0, b0, n0, kbase, tid);
    CP_COMMIT();

    for (int ch = 0; ch < NCH; ch++) {
        if (ch < NCH - 1) {
            load_chunk(sb, (ch + 1) & 1, b0, n0, kbase + (ch + 1) * BKC, tid);
            CP_COMMIT();
            CP_WAIT(1);
        } else {
            CP_WAIT(0);
        }
        __syncthreads();

        uint32_t st = sb + (ch & 1) * STAGE;
#pragma unroll
        for (int kk = 0; kk < BKC; kk += 16) {
            uint32_t ah[2][4], al[2][4];
#pragma unroll
            for (int mb = 0; mb < 2; mb++) {
                int row = wm * 32 + mb * 16 + (lane & 15);
                uint32_t off = row * 80 + (kk + (lane >> 4) * 8) * 2;
                ldsm_x4(ah[mb][0], ah[mb][1], ah[mb][2], ah[mb][3], st + ST_AH + off);
                ldsm_x4(al[mb][0], al[mb][1], al[mb][2], al[mb][3], st + ST_AL + off);
            }
            uint32_t bh[4][2], bl[4][2];
#pragma unroll
            for (int np = 0; np < 2; np++) {
                int row = wn * 32 + np * 16 + (lane & 7) + ((lane >> 4) << 3);
                uint32_t off = row * 80 + (kk + ((lane >> 3) & 1) * 8) * 2;
                ldsm_x4(bh[2 * np][0], bh[2 * np][1], bh[2 * np + 1][0], bh[2 * np + 1][1],
                        st + ST_BH + off);
                ldsm_x4(bl[2 * np][0], bl[2 * np][1], bl[2 * np + 1][0], bl[2 * np + 1][1],
                        st + ST_BL + off);
            }
#pragma unroll
            for (int mb = 0; mb < 2; mb++)
#pragma unroll
                for (int nb = 0; nb < 4; nb++) {
                    mma16816(c[mb][nb], ah[mb], bh[nb]);
                    mma16816(c[mb][nb], ah[mb], bl[nb]);
                    mma16816(c[mb][nb], al[mb], bh[nb]);
                }
        }
        __syncthreads();
    }

    // ---- epilogue: accumulators -> smem, per-row dot with x ----
    float* Us = (float*)smem;                     // 128 x LDU fp32 (reuses buf0)
#pragma unroll
    for (int mb = 0; mb < 2; mb++) {
        int row = wm * 32 + mb * 16 + (lane >> 2);
#pragma unroll
        for (int nb = 0; nb < 4; nb++) {
            int col = wn * 32 + nb * 8 + (lane & 3) * 2;
            *(float2*)(Us + row * LDU + col)       = make_float2(c[mb][nb][0], c[mb][nb][1]);
            *(float2*)(Us + (row + 8) * LDU + col) = make_float2(c[mb][nb][2], c[mb][nb][3]);
        }
    }
    __syncthreads();

    {
        int row = tid >> 1, half = tid & 1;       // 2 threads per row, 32 cols each
        const float4* xr = (const float4*)(x + (size_t)(b0 + row) * ND + n0 + half * 32);
        const float* ur = Us + row * LDU + half * 32;
        float s = 0.0f;
#pragma unroll
        for (int q = 0; q < 8; q++) {
            float4 v = xr[q];
            s = fmaf(ur[4 * q + 0], v.x, s);
            s = fmaf(ur[4 * q + 1], v.y, s);
            s = fmaf(ur[4 * q + 2], v.z, s);
            s = fmaf(ur[4 * q + 3], v.w, s);
        }
        s += __shfl_xor_sync(0xffffffffu, s, 1);
        if (half == 0)
            g_partial[(blockIdx.x * NCH + kz) * NB + b0 + row] = s;
    }

    // ---- fused finalize: last CTA of this b-tile sums 32 fixed slots ----
    __threadfence();
    __shared__ unsigned s_done;
    if (tid == 0) s_done = atomicAdd(&g_ctr[blockIdx.y], 1u);
    __syncthreads();
    if (s_done == 31u) {
        __threadfence();
        if (tid < 128) {
            int b = b0 + tid;
            float t = 0.0f;
#pragma unroll
            for (int k = 0; k < 32; k++) t += g_partial[k * NB + b];
            out[b] = g_norm[b] + t * t;
        }
    }
}

// ---------------- launch ----------------
extern "C" void kernel_launch(void* const* d_in, const int* in_sizes, int n_in,
                              void* d_out, int out_size) {
    const float* x    = (const float*)d_in[0];   // [1024, 512]
    const float* xdot = (const float*)d_in[1];   // [1024, 512]
    const float* W    = (const float*)d_in[2];   // [512, 512]
    float* out = (float*)d_out;                  // [1024]

    cudaFuncSetAttribute(stm_mma, cudaFuncAttributeMaxDynamicSharedMemorySize, SMEM_MMA);

    stm_prep<<<384, 256>>>(xdot, W);
    stm_mma<<<dim3(8, 8, 4), 256, SMEM_MMA>>>(x, out);
}